// round 1
// baseline (speedup 1.0000x reference)
#include <cuda_runtime.h>
#include <math.h>

// Shapes: F fields (2,3,128,128,128) = 12,582,912 floats each
//         I/S volumes (2,1,128,128,128) = 4,194,304 floats each (2 independent 128^3 vols)
#define DD   128
#define HW   (128*128)
#define VOL  (128*128*128)
#define NF   12582912
#define NV   4194304

// Scratch: xy-box-mean for 4 arrays (I_0, I_0R, I_1, I_1R) x 2 batch vols = 8 volumes
__device__ float  g_ys[8 * VOL];
// Accumulators: [0]=reg SSD, [1..3]=pair0 (gp,gg,pp), [4..6]=pair1, [7,8]=tv0(prod,add), [9,10]=tv1
__device__ double g_acc[16];

__global__ void k_zero() {
    if (threadIdx.x < 16) g_acc[threadIdx.x] = 0.0;
}

// ---------------------------------------------------------------------------
// Fused x+y box pass (per d-plane, h-tiles of 32). Zero padding = halo zeros.
// Writes xy-mean (scaled by 0.2 per axis, matching the reference's per-axis 1/5).
// ---------------------------------------------------------------------------
__global__ void __launch_bounds__(256) k_xy(
    const float* __restrict__ I0, const float* __restrict__ I0R,
    const float* __restrict__ I1, const float* __restrict__ I1R)
{
    __shared__ float raw[36][132];   // rows h0-2..h0+33, cols w -2..129 (shifted +2)
    __shared__ float xs[36][128];

    int b   = blockIdx.x;            // 4096 blocks: v(8) * d(128) * ht(4)
    int v   = b >> 9;
    int rem = b & 511;
    int d   = rem >> 2;
    int h0  = (rem & 3) << 5;

    const float* srcs[4] = {I0, I0R, I1, I1R};
    const float* src = srcs[v >> 1] + (v & 1) * VOL;
    float*       dst = g_ys + v * VOL;
    int tid = threadIdx.x;

    // main load (coalesced) with h bounds -> zeros
    for (int idx = tid; idx < 36 * 128; idx += 256) {
        int r = idx >> 7, w = idx & 127;
        int h = h0 - 2 + r;
        raw[r][w + 2] = (h >= 0 && h < 128) ? src[d * HW + h * 128 + w] : 0.f;
    }
    // w halo zeros (cols 0,1,130,131)
    for (int idx = tid; idx < 36 * 4; idx += 256) {
        int r = idx >> 2, c = idx & 3;
        raw[r][(c < 2) ? c : (c + 128)] = 0.f;
    }
    __syncthreads();

    // x-pass: 5-tap over w
    for (int idx = tid; idx < 36 * 128; idx += 256) {
        int r = idx >> 7, w = idx & 127;
        float s = raw[r][w] + raw[r][w + 1] + raw[r][w + 2] + raw[r][w + 3] + raw[r][w + 4];
        xs[r][w] = s * 0.2f;
    }
    __syncthreads();

    // y-pass: 5-tap over h; output rows r -> local xs rows r..r+4
    for (int idx = tid; idx < 32 * 128; idx += 256) {
        int r = idx >> 7, w = idx & 127;
        float s = xs[r][w] + xs[r + 1][w] + xs[r + 2][w] + xs[r + 3][w] + xs[r + 4][w];
        dst[d * HW + (h0 + r) * 128 + w] = s * 0.2f;
    }
}

// ---------------------------------------------------------------------------
// z box pass (register sliding window over d) fused with the 3 LCC reductions.
// 1024 blocks: pair(2) * n(2) * seg(4, 32 d-planes each) * hp(64, 2 h-rows each)
// ---------------------------------------------------------------------------
__global__ void __launch_bounds__(256) k_z(
    const float* __restrict__ I0, const float* __restrict__ I0R,
    const float* __restrict__ I1, const float* __restrict__ I1R)
{
    int b    = blockIdx.x;
    int pair = b >> 9;
    int rem  = b & 511;
    int n    = rem >> 8;
    int rem2 = rem & 255;
    int seg  = rem2 >> 6;
    int hp   = rem2 & 63;

    int tid = threadIdx.x;
    int w   = tid & 127;
    int h   = hp * 2 + (tid >> 7);

    const float* gt  = (pair ? I1  : I0)  + n * VOL;
    const float* pr  = (pair ? I1R : I0R) + n * VOL;
    const float* ysg = g_ys + ((pair * 2 + 0) * 2 + n) * VOL;
    const float* ysp = g_ys + ((pair * 2 + 1) * 2 + n) * VOL;

    int off = h * 128 + w;
    int d0  = seg * 32;

    // window regs hold ys[dout-2 .. dout+2] at dout = d0
    float g0 = (d0 - 2 >= 0) ? ysg[off + (d0 - 2) * HW] : 0.f;
    float g1 = (d0 - 1 >= 0) ? ysg[off + (d0 - 1) * HW] : 0.f;
    float g2 = ysg[off + d0 * HW];
    float g3 = ysg[off + (d0 + 1) * HW];
    float g4 = ysg[off + (d0 + 2) * HW];
    float p0 = (d0 - 2 >= 0) ? ysp[off + (d0 - 2) * HW] : 0.f;
    float p1 = (d0 - 1 >= 0) ? ysp[off + (d0 - 1) * HW] : 0.f;
    float p2 = ysp[off + d0 * HW];
    float p3 = ysp[off + (d0 + 1) * HW];
    float p4 = ysp[off + (d0 + 2) * HW];

    float sgp = 0.f, sgg = 0.f, spp = 0.f;

#pragma unroll 4
    for (int dout = d0; dout < d0 + 32; ++dout) {
        float mg = (g0 + g1 + g2 + g3 + g4) * 0.2f;
        float mp = (p0 + p1 + p2 + p3 + p4) * 0.2f;
        float dg = gt[off + dout * HW] - mg;
        float dp = pr[off + dout * HW] - mp;
        sgp += dg * dp;
        sgg += dg * dg;
        spp += dp * dp;
        g0 = g1; g1 = g2; g2 = g3; g3 = g4;
        p0 = p1; p1 = p2; p2 = p3; p3 = p4;
        int dn = dout + 3;
        g4 = (dn < 128) ? ysg[off + dn * HW] : 0.f;
        p4 = (dn < 128) ? ysp[off + dn * HW] : 0.f;
    }

    // block reduce 3 values
    __shared__ float sh[3][8];
    unsigned lane = tid & 31, wd = tid >> 5;
#pragma unroll
    for (int o = 16; o; o >>= 1) {
        sgp += __shfl_down_sync(0xffffffffu, sgp, o);
        sgg += __shfl_down_sync(0xffffffffu, sgg, o);
        spp += __shfl_down_sync(0xffffffffu, spp, o);
    }
    if (lane == 0) { sh[0][wd] = sgp; sh[1][wd] = sgg; sh[2][wd] = spp; }
    __syncthreads();
    if (tid == 0) {
        float a = 0.f, b2 = 0.f, c = 0.f;
#pragma unroll
        for (int i = 0; i < 8; ++i) { a += sh[0][i]; b2 += sh[1][i]; c += sh[2][i]; }
        atomicAdd(&g_acc[1 + 3 * pair], (double)a);
        atomicAdd(&g_acc[2 + 3 * pair], (double)b2);
        atomicAdd(&g_acc[3 + 3 * pair], (double)c);
    }
}

// ---------------------------------------------------------------------------
// reg field: SSD over F fields (float4 grid-stride)
// ---------------------------------------------------------------------------
__global__ void __launch_bounds__(256) k_reg(
    const float4* __restrict__ A, const float4* __restrict__ B, int n4)
{
    float s = 0.f;
    for (int i = blockIdx.x * blockDim.x + threadIdx.x; i < n4; i += gridDim.x * blockDim.x) {
        float4 a = A[i], b = B[i];
        float d0 = a.x - b.x, d1 = a.y - b.y, d2 = a.z - b.z, d3 = a.w - b.w;
        s += d0 * d0 + d1 * d1 + d2 * d2 + d3 * d3;
    }
    __shared__ float sh[8];
    int tid = threadIdx.x;
    unsigned lane = tid & 31, wd = tid >> 5;
#pragma unroll
    for (int o = 16; o; o >>= 1) s += __shfl_down_sync(0xffffffffu, s, o);
    if (lane == 0) sh[wd] = s;
    __syncthreads();
    if (tid == 0) {
        float a = 0.f;
#pragma unroll
        for (int i = 0; i < 8; ++i) a += sh[i];
        atomicAdd(&g_acc[0], (double)a);
    }
}

// ---------------------------------------------------------------------------
// Tversky sums: sum(S*Sg) and sum(S+Sg)
// ---------------------------------------------------------------------------
__global__ void __launch_bounds__(256) k_tv(
    const float4* __restrict__ S, const float4* __restrict__ Sg, int n4, int accIdx)
{
    float sp = 0.f, sa = 0.f;
    for (int i = blockIdx.x * blockDim.x + threadIdx.x; i < n4; i += gridDim.x * blockDim.x) {
        float4 a = S[i], b = Sg[i];
        sp += a.x * b.x + a.y * b.y + a.z * b.z + a.w * b.w;
        sa += a.x + b.x + a.y + b.y + a.z + b.z + a.w + b.w;
    }
    __shared__ float sh[2][8];
    int tid = threadIdx.x;
    unsigned lane = tid & 31, wd = tid >> 5;
#pragma unroll
    for (int o = 16; o; o >>= 1) {
        sp += __shfl_down_sync(0xffffffffu, sp, o);
        sa += __shfl_down_sync(0xffffffffu, sa, o);
    }
    if (lane == 0) { sh[0][wd] = sp; sh[1][wd] = sa; }
    __syncthreads();
    if (tid == 0) {
        float a = 0.f, b = 0.f;
#pragma unroll
        for (int i = 0; i < 8; ++i) { a += sh[0][i]; b += sh[1][i]; }
        atomicAdd(&g_acc[accIdx],     (double)a);
        atomicAdd(&g_acc[accIdx + 1], (double)b);
    }
}

// ---------------------------------------------------------------------------
// Finalize scalar
// ---------------------------------------------------------------------------
__global__ void k_final(float* out) {
    double reg = sqrt(g_acc[0]) / (double)NF;
    double l = 0.0;
    for (int p = 0; p < 2; ++p) {
        double gp = g_acc[1 + 3 * p], gg = g_acc[2 + 3 * p], pp = g_acc[3 + 3 * p];
        double den = gg * pp;
        if (den < 1e-5) den = 1e-5;
        l += -(gp * gp / den) / (double)NV;
    }
    double t = 0.0;
    for (int p = 0; p < 2; ++p) {
        double prod = g_acc[7 + 2 * p], add = g_acc[8 + 2 * p];
        double den = add;
        if (den < 1e-5) den = 1e-5;
        t += -prod / den;
    }
    out[0] = (float)(reg + 10.0 * l + 10.0 * t);
}

extern "C" void kernel_launch(void* const* d_in, const int* in_sizes, int n_in,
                              void* d_out, int out_size) {
    const float* F0  = (const float*)d_in[0];
    const float* F0g = (const float*)d_in[1];
    const float* I0  = (const float*)d_in[2];
    const float* I0R = (const float*)d_in[3];
    const float* I1  = (const float*)d_in[4];
    const float* I1R = (const float*)d_in[5];
    const float* S0  = (const float*)d_in[6];
    const float* S0g = (const float*)d_in[7];
    const float* S1  = (const float*)d_in[8];
    const float* S1g = (const float*)d_in[9];

    k_zero<<<1, 32>>>();
    k_xy<<<4096, 256>>>(I0, I0R, I1, I1R);
    k_z<<<1024, 256>>>(I0, I0R, I1, I1R);
    k_reg<<<1024, 256>>>((const float4*)F0, (const float4*)F0g, NF / 4);
    k_tv<<<512, 256>>>((const float4*)S0, (const float4*)S0g, NV / 4, 7);
    k_tv<<<512, 256>>>((const float4*)S1, (const float4*)S1g, NV / 4, 9);
    k_final<<<1, 1>>>((float*)d_out);
}